// round 13
// baseline (speedup 1.0000x reference)
#include <cuda_runtime.h>
#include <cstdint>

#define NB 128
#define NT 512
#define BB 16
#define TT 1024
#define DD 1024
#define SS 512
#define MM 16
#define KSPLIT 8
#define KBL 384                    // k per block
#define CBB 6176                   // bytes per cb staging region (6144 + pad)

// ---------------- persistent state (device globals; no allocation) ----------
__device__ float g_h[BB * DD];
__device__ float g_cbuf[2][BB * DD];            // parity double buffer for c
__device__ float g_ctx[BB * DD];
__device__ float g_bias[4 * DD];
__device__ float g_gpart[KSPLIT][BB][4 * DD];   // 2 MB
__device__ unsigned g_cnt_grp[8 * 32];          // group counters, 128B apart
__device__ unsigned g_cnt_root;
__device__ int g_flags[NB * 8];

__device__ __forceinline__ float sigf(float x) {
    return __fdividef(1.0f, 1.0f + __expf(-x));
}
__device__ __forceinline__ float tanhfast(float x) {
    const float xc = fminf(fmaxf(x, -15.0f), 15.0f);
    const float e  = __expf(2.0f * xc);
    return __fdividef(e - 1.0f, e + 1.0f);
}

// Grid barrier: tree arrival (8 groups of 16 -> root), distributed release,
// pure-spin detect (each block polls its own flag line).
__device__ __forceinline__ void grid_barrier(int gen) {
    __syncthreads();
    if (threadIdx.x == 0) {
        __threadfence();
        const int g = blockIdx.x >> 4;
        if (atomicAdd(&g_cnt_grp[g * 32], 1u) == 15u) {
            g_cnt_grp[g * 32] = 0u;
            if (atomicAdd(&g_cnt_root, 1u) == 7u) {
                g_cnt_root = 0u;
                __threadfence();
                #pragma unroll 8
                for (int i = 0; i < NB; ++i) g_flags[i * 8] = gen;
            }
        }
        volatile int* f = &g_flags[blockIdx.x * 8];
        while (*f != gen) { }
        __threadfence();
    }
    __syncthreads();
}

extern __shared__ float smem[];

__device__ __forceinline__ uint32_t swz(uint32_t L) {
    return L ^ ((L >> 3) & 0x70u);
}

__global__ __launch_bounds__(NT, 1) void tts_kernel(
    const float* __restrict__ x_in,    // [B,T,D]
    const float* __restrict__ memv,    // [B,S,D]
    const int*   __restrict__ lens,    // [B]
    const float* __restrict__ W_ih,    // [4096,2048]
    const float* __restrict__ W_hh,    // [4096,1024]
    const float* __restrict__ b_ih,    // [4096]
    const float* __restrict__ b_hh,    // [4096]
    const float* __restrict__ Wg_w,    // [48,1024]
    const float* __restrict__ Wg_b,    // [48]
    float* __restrict__ out)
{
    const int bid = blockIdx.x;
    const int tid = threadIdx.x;
    char* smb = reinterpret_cast<char*>(smem);

    // smem layout (floats):
    //   [0, 6176)      staging (4 regions x 6176 B)
    //   [6176, 6272)   phi/ksi/binv/alpha
    //   [6272, 7296)   sh_h
    //   [7296, 7808)   sh_watt
    //   [7808, 7824)   sh_skip
    //   [7824, 9872)   red (float4[512])
    float* sh_phi   = smem + 6176;
    float* sh_ksi   = smem + 6224;
    float* sh_binv  = smem + 6240;
    float* sh_alpha = smem + 6256;
    float* sh_h     = smem + 6272;
    float* sh_watt  = smem + 7296;
    int*   sh_skip  = reinterpret_cast<int*>(smem + 7808);
    float4* red     = reinterpret_cast<float4*>(smem + 7824);

    float* out_ctx   = out;
    float* out_align = out + BB * DD;
    float* out_term  = out + BB * DD + (size_t)BB * TT * SS;

    int bgen = 0;

    for (int i = bid * NT + tid; i < BB * DD; i += NB * NT) {
        g_h[i] = 0.0f; g_cbuf[0][i] = 0.0f; g_cbuf[1][i] = 0.0f; g_ctx[i] = 0.0f;
    }
    for (int i = bid * NT + tid; i < 4 * DD; i += NB * NT)
        g_bias[i] = b_ih[i] + b_hh[i];

    // GEMM mapping: 16 j-tiles (256 j each) x 8 k-splits (384 k each)
    const int jt = bid >> 3;            // 0..15
    const int kb = bid & 7;             // 0..7
    const int kbase = kb * KBL;

    const int jg    = tid >> 4;         // 0..31 -> 8 rows each
    const int lane4 = tid & 15;
    const int bg    = lane4 & 1;
    const int ksl   = lane4 >> 1;
    const int j0    = jt * 256 + jg * 8;

    const float* wih = W_ih + (size_t)j0 * 2048;
    const float* whh = W_hh + (size_t)j0 * 1024;

    // fused-phase mapping: every block owns (b2, d0); one writer per b2
    const int  b2     = bid >> 3;
    const int  d0     = (bid & 7) * 128;
    const bool writer = (bid & 7) == 0;

    // weight loader (t-invariant addresses)
    float2 wA[8], wB[8];
    auto ldw = [&](float2* dst, int i) {
        const int k = kbase + (i * 8 + ksl) * 2;
        if (k < 2048) {
            const float* p = wih + k;
            #pragma unroll
            for (int a = 0; a < 8; ++a)
                dst[a] = *reinterpret_cast<const float2*>(p + (size_t)a * 2048);
        } else {
            const float* p = whh + (k - 2048);
            #pragma unroll
            for (int a = 0; a < 8; ++a)
                dst[a] = *reinterpret_cast<const float2*>(p + (size_t)a * 1024);
        }
    };

    // x_in pre-stager (k < 1024 quads only) for time index tt
    auto prestage_x = [&](int tt) {
        #pragma unroll
        for (int r = 0; r < 3; ++r) {
            const int qi = r * NT + tid;         // < 1536
            const int b  = qi / 96;
            const int kq = qi - b * 96;
            const int k  = kbase + kq * 4;
            if (k < DD) {
                const float4 v = *reinterpret_cast<const float4*>(
                    &x_in[((size_t)b * TT + tt) * DD + k]);
                const int cb = b >> 2, bl = b & 3;
                char* base = smb + cb * CBB;
                const int kl = kq * 4;
                *reinterpret_cast<float*>(base + swz((uint32_t)((kl + 0) * 16 + bl * 4))) = v.x;
                *reinterpret_cast<float*>(base + swz((uint32_t)((kl + 1) * 16 + bl * 4))) = v.y;
                *reinterpret_cast<float*>(base + swz((uint32_t)((kl + 2) * 16 + bl * 4))) = v.z;
                *reinterpret_cast<float*>(base + swz((uint32_t)((kl + 3) * 16 + bl * 4))) = v.w;
            }
        }
    };

    prestage_x(0);        // x(0) into staging before first step
    ldw(wA, 0);           // first weights in flight across the barrier
    grid_barrier(++bgen);

    for (int t = 0; t < TT; ++t) {
        // ===== stage ctx/h quads (k >= 1024); x quads already pre-staged ===
        #pragma unroll
        for (int r = 0; r < 3; ++r) {
            const int qi = r * NT + tid;         // < 1536
            const int b  = qi / 96;
            const int kq = qi - b * 96;
            const int k  = kbase + kq * 4;
            if (k >= DD) {
                float4 v;
                if (k < 2 * DD)
                    v = *reinterpret_cast<const float4*>(&g_ctx[b * DD + (k - DD)]);
                else
                    v = *reinterpret_cast<const float4*>(&g_h[b * DD + (k - 2 * DD)]);
                const int cb = b >> 2, bl = b & 3;
                char* base = smb + cb * CBB;
                const int kl = kq * 4;
                *reinterpret_cast<float*>(base + swz((uint32_t)((kl + 0) * 16 + bl * 4))) = v.x;
                *reinterpret_cast<float*>(base + swz((uint32_t)((kl + 1) * 16 + bl * 4))) = v.y;
                *reinterpret_cast<float*>(base + swz((uint32_t)((kl + 2) * 16 + bl * 4))) = v.z;
                *reinterpret_cast<float*>(base + swz((uint32_t)((kl + 3) * 16 + bl * 4))) = v.w;
            }
        }
        __syncthreads();

        // ====== gates GEMM: 8 rows/thread, float2 weight double-buffer =====
        {
            unsigned long long acc[8][4];
            #pragma unroll
            for (int a = 0; a < 8; ++a)
                #pragma unroll
                for (int p = 0; p < 4; ++p) acc[a][p] = 0ull;

            const char* xb0 = smb + (bg * 2) * CBB;

            auto compute = [&](const float2* w, int i) {
                const int kp = i * 8 + ksl;
                #pragma unroll
                for (int q = 0; q < 2; ++q) {
                    const int kl = kp * 2 + q;
                    const uint32_t L = swz((uint32_t)(kl * 16));
                    const double2 d0v = *reinterpret_cast<const double2*>(xb0 + L);
                    const double2 d1v = *reinterpret_cast<const double2*>(xb0 + CBB + L);
                    const unsigned long long xv0 = __double_as_longlong(d0v.x);
                    const unsigned long long xv1 = __double_as_longlong(d0v.y);
                    const unsigned long long xv2 = __double_as_longlong(d1v.x);
                    const unsigned long long xv3 = __double_as_longlong(d1v.y);
                    #pragma unroll
                    for (int a = 0; a < 8; ++a) {
                        const float wv = q ? w[a].y : w[a].x;
                        unsigned long long w2;
                        asm("mov.b64 %0, {%1, %1};" : "=l"(w2) : "r"(__float_as_uint(wv)));
                        asm("fma.rn.f32x2 %0, %1, %2, %0;" : "+l"(acc[a][0]) : "l"(w2), "l"(xv0));
                        asm("fma.rn.f32x2 %0, %1, %2, %0;" : "+l"(acc[a][1]) : "l"(w2), "l"(xv1));
                        asm("fma.rn.f32x2 %0, %1, %2, %0;" : "+l"(acc[a][2]) : "l"(w2), "l"(xv2));
                        asm("fma.rn.f32x2 %0, %1, %2, %0;" : "+l"(acc[a][3]) : "l"(w2), "l"(xv3));
                    }
                }
            };

            #pragma unroll 1
            for (int ii = 0; ii < 12; ++ii) {
                ldw(wB, 2 * ii + 1);
                compute(wA, 2 * ii);
                if (ii < 11) ldw(wA, 2 * ii + 2);
                compute(wB, 2 * ii + 1);
            }

            #pragma unroll
            for (int off = 2; off <= 8; off <<= 1) {
                #pragma unroll
                for (int a = 0; a < 8; ++a)
                    #pragma unroll
                    for (int p = 0; p < 4; ++p) {
                        unsigned lo = (unsigned)acc[a][p];
                        unsigned hi = (unsigned)(acc[a][p] >> 32);
                        lo = __shfl_xor_sync(0xFFFFFFFFu, lo, off);
                        hi = __shfl_xor_sync(0xFFFFFFFFu, hi, off);
                        unsigned long long o = ((unsigned long long)hi << 32) | lo;
                        asm("add.rn.f32x2 %0, %0, %1;" : "+l"(acc[a][p]) : "l"(o));
                    }
            }

            #pragma unroll
            for (int a = 0; a < 8; ++a) {
                if (a == ksl) {
                    const int j = j0 + a;
                    #pragma unroll
                    for (int p = 0; p < 4; ++p) {
                        const int b0 = bg * 8 + 2 * p;
                        const unsigned long long v = acc[a][p];
                        g_gpart[kb][b0][j]     = __uint_as_float((unsigned)v);
                        g_gpart[kb][b0 + 1][j] = __uint_as_float((unsigned)(v >> 32));
                    }
                }
            }
        }
        grid_barrier(++bgen);  // B1: gates(t) complete

        // ===== fused phase: LSTM+phi+attn (redundant per b) + ctx GEMV =====
        {
            const float* cin  = g_cbuf[t & 1]       + b2 * DD;
            float*       cout = g_cbuf[(t & 1) ^ 1] + b2 * DD;

            {
                const int e = tid;   // pair index, 0..511
                const float2* gb = reinterpret_cast<const float2*>(g_bias);
                float2 gi = gb[e],        gf = gb[512 + e];
                float2 gg = gb[1024 + e], go = gb[1536 + e];
                #pragma unroll
                for (int q = 0; q < KSPLIT; ++q) {
                    const float2* gp = reinterpret_cast<const float2*>(g_gpart[q][b2]);
                    float2 v;
                    v = gp[e];        gi.x += v.x; gi.y += v.y;
                    v = gp[512 + e];  gf.x += v.x; gf.y += v.y;
                    v = gp[1024 + e]; gg.x += v.x; gg.y += v.y;
                    v = gp[1536 + e]; go.x += v.x; go.y += v.y;
                }
                const float2 cold = reinterpret_cast<const float2*>(cin)[e];
                float2 cn, hn;
                cn.x = sigf(gf.x) * cold.x + sigf(gi.x) * tanhfast(gg.x);
                cn.y = sigf(gf.y) * cold.y + sigf(gi.y) * tanhfast(gg.y);
                hn.x = sigf(go.x) * tanhfast(cn.x);
                hn.y = sigf(go.y) * tanhfast(cn.y);
                reinterpret_cast<float2*>(sh_h)[e] = hn;
                if (writer) {
                    reinterpret_cast<float2*>(cout)[e] = cn;
                    reinterpret_cast<float2*>(g_h + b2 * DD)[e] = hn;
                }
            }
            __syncthreads();

            // phi = h @ Wg_w^T + Wg_b  (16 warps x 3 rows)
            {
                const int w = tid >> 5, lane = tid & 31;
                float hreg[32];
                #pragma unroll
                for (int i = 0; i < 32; ++i) hreg[i] = sh_h[i * 32 + lane];
                #pragma unroll
                for (int mi = 0; mi < 3; ++mi) {
                    const int mm = w * 3 + mi;
                    const float* wr = Wg_w + (size_t)mm * DD;
                    float acc = 0.0f;
                    #pragma unroll
                    for (int i = 0; i < 32; ++i) acc += wr[i * 32 + lane] * hreg[i];
                    #pragma unroll
                    for (int off = 16; off; off >>= 1)
                        acc += __shfl_xor_sync(0xFFFFFFFFu, acc, off);
                    if (lane == 0) sh_phi[mm] = acc + Wg_b[mm];
                }
            }
            __syncthreads();

            if (tid < 32) {
                const int m = tid & 15;
                const float pk = sh_phi[m];
                const float pb = sh_phi[MM + m];
                const float pa = sh_phi[2 * MM + m];
                float mx = pa;
                #pragma unroll
                for (int off = 1; off < 16; off <<= 1)
                    mx = fmaxf(mx, __shfl_xor_sync(0xFFFFFFFFu, mx, off, 16));
                const float e = __expf(pa - mx);
                float sum = e;
                #pragma unroll
                for (int off = 1; off < 16; off <<= 1)
                    sum += __shfl_xor_sync(0xFFFFFFFFu, sum, off, 16);
                if (tid < 16) {
                    sh_alpha[m] = e / sum;
                    sh_ksi[m]   = __expf(pk);
                    sh_binv[m]  = __expf(-pb);
                }
            }
            __syncthreads();

            // attention weights (one s per thread) + warp-chunk skip flags
            {
                const int s = tid;            // NT == SS
                const int w = tid >> 5, lane = tid & 31;
                const float fs = (float)s;
                float aw = 0.0f, ar = 0.0f;
                #pragma unroll
                for (int m = 0; m < MM; ++m) {
                    const float binv = sh_binv[m];
                    const float z  = (fs - sh_ksi[m]) * binv;
                    const float hb = 0.5f * binv;
                    const float fr = sigf(z + hb);
                    const float fl = sigf(z - hb);
                    const float al = sh_alpha[m];
                    aw += al * (fr - fl);
                    ar += al * fr;
                }
                sh_watt[s] = aw;
                float mx = aw;
                #pragma unroll
                for (int off = 16; off; off >>= 1)
                    mx = fmaxf(mx, __shfl_xor_sync(0xFFFFFFFFu, mx, off));
                if (lane == 0) sh_skip[w] = (mx < 1e-8f);
                if (writer) {
                    out_align[((size_t)b2 * TT + t) * SS + s] = aw;
                    if (t == TT - 1 && s == lens[b2] - 1) out_term[b2] = 1.0f - ar;
                }
            }
            __syncthreads();

            // ctx GEMV: this block's (b2, d0) slice; skip near-zero s chunks
            {
                const int w = tid >> 5, lane = tid & 31;
                float4 acc = make_float4(0.f, 0.f, 0.f, 0.f);
                if (!sh_skip[w]) {
                    const float* mb = memv + (size_t)b2 * SS * DD + d0 + lane * 4;
                    const int sbase = w * 32;
                    #pragma unroll 4
                    for (int si = 0; si < 32; ++si) {
                        const int s = sbase + si;
                        const float wv = sh_watt[s];
                        const float4 mv = *reinterpret_cast<const float4*>(mb + (size_t)s * DD);
                        acc.x += wv * mv.x; acc.y += wv * mv.y;
                        acc.z += wv * mv.z; acc.w += wv * mv.w;
                    }
                }
                red[w * 32 + lane] = acc;
                __syncthreads();
                if (tid < 32) {
                    float4 r = red[tid];
                    #pragma unroll
                    for (int q = 1; q < 16; ++q) {
                        const float4 v = red[q * 32 + tid];
                        r.x += v.x; r.y += v.y; r.z += v.z; r.w += v.w;
                    }
                    const int di = d0 + tid * 4;
                    *reinterpret_cast<float4*>(&g_ctx[b2 * DD + di]) = r;
                    if (t == TT - 1)
                        *reinterpret_cast<float4*>(&out_ctx[b2 * DD + di]) = r;
                }
            }

            // overlap with B3: next step's x quads + first weights
            if (t + 1 < TT) prestage_x(t + 1);
            ldw(wA, 0);
        }
        grid_barrier(++bgen);  // B3: h, c, ctx ready for next step
    }
}

extern "C" void kernel_launch(void* const* d_in, const int* in_sizes, int n_in,
                              void* d_out, int out_size) {
    (void)in_sizes; (void)n_in; (void)out_size;
    const float* x_in  = (const float*)d_in[0];
    const float* memv  = (const float*)d_in[1];
    const int*   lens  = (const int*)  d_in[2];
    const float* W_ih  = (const float*)d_in[3];
    const float* W_hh  = (const float*)d_in[4];
    const float* b_ih  = (const float*)d_in[5];
    const float* b_hh  = (const float*)d_in[6];
    const float* Wg_w  = (const float*)d_in[7];
    const float* Wg_b  = (const float*)d_in[8];
    tts_kernel<<<NB, NT, 40960>>>(x_in, memv, lens, W_ih, W_hh,
                                  b_ih, b_hh, Wg_w, Wg_b, (float*)d_out);
}

// round 14
// speedup vs baseline: 1.0802x; 1.0802x over previous
#include <cuda_runtime.h>
#include <cstdint>

#define NB 128
#define NT 512
#define BB 16
#define TT 1024
#define DD 1024
#define SS 512
#define MM 16
#define KSPLIT 8
#define KBL 384                    // k per block
#define CBB 6176                   // bytes per cb staging region (6144 + pad)

// ---------------- persistent state (device globals; no allocation) ----------
__device__ float g_h[BB * DD];
__device__ float g_cbuf[2][BB * DD];            // parity double buffer for c
__device__ float g_ctx[BB * DD];
__device__ float g_bias[4 * DD];
__device__ float g_gpart[KSPLIT][BB][4 * DD];   // 2 MB
__device__ unsigned g_cnt_grp[8 * 32];          // group counters, 128B apart
__device__ unsigned g_cnt_root;
__device__ int g_flags[NB * 8];

__device__ __forceinline__ float sigf(float x) {
    return __fdividef(1.0f, 1.0f + __expf(-x));
}
__device__ __forceinline__ float tanhfast(float x) {
    const float xc = fminf(fmaxf(x, -15.0f), 15.0f);
    const float e  = __expf(2.0f * xc);
    return __fdividef(e - 1.0f, e + 1.0f);
}

// Grid barrier: tree arrival (8 groups of 16 -> root), distributed release.
__device__ __forceinline__ void grid_barrier(int gen) {
    __syncthreads();
    if (threadIdx.x == 0) {
        __threadfence();
        const int g = blockIdx.x >> 4;
        if (atomicAdd(&g_cnt_grp[g * 32], 1u) == 15u) {
            g_cnt_grp[g * 32] = 0u;
            if (atomicAdd(&g_cnt_root, 1u) == 7u) {
                g_cnt_root = 0u;
                __threadfence();
                #pragma unroll 8
                for (int i = 0; i < NB; ++i) g_flags[i * 8] = gen;
            }
        }
        volatile int* f = &g_flags[blockIdx.x * 8];
        while (*f != gen) { __nanosleep(16); }
        __threadfence();
    }
    __syncthreads();
}

extern __shared__ float smem[];

__device__ __forceinline__ uint32_t swz(uint32_t L) {
    return L ^ ((L >> 3) & 0x70u);
}

__global__ __launch_bounds__(NT, 1) void tts_kernel(
    const float* __restrict__ x_in,    // [B,T,D]
    const float* __restrict__ memv,    // [B,S,D]
    const int*   __restrict__ lens,    // [B]
    const float* __restrict__ W_ih,    // [4096,2048]
    const float* __restrict__ W_hh,    // [4096,1024]
    const float* __restrict__ b_ih,    // [4096]
    const float* __restrict__ b_hh,    // [4096]
    const float* __restrict__ Wg_w,    // [48,1024]
    const float* __restrict__ Wg_b,    // [48]
    float* __restrict__ out)
{
    const int bid = blockIdx.x;
    const int tid = threadIdx.x;
    char* smb = reinterpret_cast<char*>(smem);

    // smem layout (floats):
    //   [0, 6176)      staging (4 regions x 6176 B)
    //   [6176, 6272)   phi/ksi/binv/alpha
    //   [6272, 7296)   sh_h
    //   [7296, 7808)   sh_watt
    //   [7808, 7840)   sh_lo[16], sh_hi[16]
    //   [7840, 9888)   red (float4[512])
    float* sh_phi   = smem + 6176;
    float* sh_ksi   = smem + 6224;
    float* sh_binv  = smem + 6240;
    float* sh_alpha = smem + 6256;
    float* sh_h     = smem + 6272;
    float* sh_watt  = smem + 7296;
    int*   sh_lo    = reinterpret_cast<int*>(smem + 7808);
    int*   sh_hi    = reinterpret_cast<int*>(smem + 7824);
    float4* red     = reinterpret_cast<float4*>(smem + 7840);

    float* out_ctx   = out;
    float* out_align = out + BB * DD;
    float* out_term  = out + BB * DD + (size_t)BB * TT * SS;

    int bgen = 0;

    for (int i = bid * NT + tid; i < BB * DD; i += NB * NT) {
        g_h[i] = 0.0f; g_cbuf[0][i] = 0.0f; g_cbuf[1][i] = 0.0f; g_ctx[i] = 0.0f;
    }
    for (int i = bid * NT + tid; i < 4 * DD; i += NB * NT)
        g_bias[i] = b_ih[i] + b_hh[i];
    grid_barrier(++bgen);

    // GEMM mapping: 16 j-tiles (256 j each) x 8 k-splits (384 k each)
    const int jt = bid >> 3;            // 0..15
    const int kb = bid & 7;             // 0..7
    const int kbase = kb * KBL;

    const int jg    = tid >> 4;         // 0..31 -> 8 rows each
    const int lane4 = tid & 15;
    const int bg    = lane4 & 1;
    const int ksl   = lane4 >> 1;
    const int j0    = jt * 256 + jg * 8;

    const float* wih = W_ih + (size_t)j0 * 2048;
    const float* whh = W_hh + (size_t)j0 * 1024;

    // fused-phase mapping: block owns (b2, d0); slice index within b2 group
    const int b2  = bid >> 3;
    const int sl8 = bid & 7;            // 0..7 slice of this b2 group
    const int d0  = sl8 * 128;

    for (int t = 0; t < TT; ++t) {
        // ========== stage x slice [16 b x 384 k] (swizzled, float4 LDG) ====
        #pragma unroll
        for (int r = 0; r < 3; ++r) {
            const int qi = r * NT + tid;         // < 1536
            const int b  = qi / 96;
            const int kq = qi - b * 96;
            const int k  = kbase + kq * 4;
            float4 v;
            if (k < DD)
                v = *reinterpret_cast<const float4*>(&x_in[((size_t)b * TT + t) * DD + k]);
            else if (k < 2 * DD)
                v = *reinterpret_cast<const float4*>(&g_ctx[b * DD + (k - DD)]);
            else
                v = *reinterpret_cast<const float4*>(&g_h[b * DD + (k - 2 * DD)]);
            const int cb = b >> 2, bl = b & 3;
            char* base = smb + cb * CBB;
            const int kl = kq * 4;
            *reinterpret_cast<float*>(base + swz((uint32_t)((kl + 0) * 16 + bl * 4))) = v.x;
            *reinterpret_cast<float*>(base + swz((uint32_t)((kl + 1) * 16 + bl * 4))) = v.y;
            *reinterpret_cast<float*>(base + swz((uint32_t)((kl + 2) * 16 + bl * 4))) = v.z;
            *reinterpret_cast<float*>(base + swz((uint32_t)((kl + 3) * 16 + bl * 4))) = v.w;
        }
        __syncthreads();

        // ====== gates GEMM: 8 rows/thread, float2 weight double-buffer =====
        {
            unsigned long long acc[8][4];
            #pragma unroll
            for (int a = 0; a < 8; ++a)
                #pragma unroll
                for (int p = 0; p < 4; ++p) acc[a][p] = 0ull;

            float2 wA[8], wB[8];

            auto ldw = [&](float2* dst, int i) {
                const int k = kbase + (i * 8 + ksl) * 2;
                if (k < 2048) {
                    const float* p = wih + k;
                    #pragma unroll
                    for (int a = 0; a < 8; ++a)
                        dst[a] = *reinterpret_cast<const float2*>(p + (size_t)a * 2048);
                } else {
                    const float* p = whh + (k - 2048);
                    #pragma unroll
                    for (int a = 0; a < 8; ++a)
                        dst[a] = *reinterpret_cast<const float2*>(p + (size_t)a * 1024);
                }
            };

            const char* xb0 = smb + (bg * 2) * CBB;

            auto compute = [&](const float2* w, int i) {
                const int kp = i * 8 + ksl;
                #pragma unroll
                for (int q = 0; q < 2; ++q) {
                    const int kl = kp * 2 + q;
                    const uint32_t L = swz((uint32_t)(kl * 16));
                    const double2 d0v = *reinterpret_cast<const double2*>(xb0 + L);
                    const double2 d1v = *reinterpret_cast<const double2*>(xb0 + CBB + L);
                    const unsigned long long xv0 = __double_as_longlong(d0v.x);
                    const unsigned long long xv1 = __double_as_longlong(d0v.y);
                    const unsigned long long xv2 = __double_as_longlong(d1v.x);
                    const unsigned long long xv3 = __double_as_longlong(d1v.y);
                    #pragma unroll
                    for (int a = 0; a < 8; ++a) {
                        const float wv = q ? w[a].y : w[a].x;
                        unsigned long long w2;
                        asm("mov.b64 %0, {%1, %1};" : "=l"(w2) : "r"(__float_as_uint(wv)));
                        asm("fma.rn.f32x2 %0, %1, %2, %0;" : "+l"(acc[a][0]) : "l"(w2), "l"(xv0));
                        asm("fma.rn.f32x2 %0, %1, %2, %0;" : "+l"(acc[a][1]) : "l"(w2), "l"(xv1));
                        asm("fma.rn.f32x2 %0, %1, %2, %0;" : "+l"(acc[a][2]) : "l"(w2), "l"(xv2));
                        asm("fma.rn.f32x2 %0, %1, %2, %0;" : "+l"(acc[a][3]) : "l"(w2), "l"(xv3));
                    }
                }
            };

            ldw(wA, 0);
            #pragma unroll 1
            for (int ii = 0; ii < 12; ++ii) {
                ldw(wB, 2 * ii + 1);
                compute(wA, 2 * ii);
                if (ii < 11) ldw(wA, 2 * ii + 2);
                compute(wB, 2 * ii + 1);
            }

            #pragma unroll
            for (int off = 2; off <= 8; off <<= 1) {
                #pragma unroll
                for (int a = 0; a < 8; ++a)
                    #pragma unroll
                    for (int p = 0; p < 4; ++p) {
                        unsigned lo = (unsigned)acc[a][p];
                        unsigned hi = (unsigned)(acc[a][p] >> 32);
                        lo = __shfl_xor_sync(0xFFFFFFFFu, lo, off);
                        hi = __shfl_xor_sync(0xFFFFFFFFu, hi, off);
                        unsigned long long o = ((unsigned long long)hi << 32) | lo;
                        asm("add.rn.f32x2 %0, %0, %1;" : "+l"(acc[a][p]) : "l"(o));
                    }
            }

            #pragma unroll
            for (int a = 0; a < 8; ++a) {
                if (a == ksl) {
                    const int j = j0 + a;
                    #pragma unroll
                    for (int p = 0; p < 4; ++p) {
                        const int b0 = bg * 8 + 2 * p;
                        const unsigned long long v = acc[a][p];
                        g_gpart[kb][b0][j]     = __uint_as_float((unsigned)v);
                        g_gpart[kb][b0 + 1][j] = __uint_as_float((unsigned)(v >> 32));
                    }
                }
            }
        }
        grid_barrier(++bgen);  // B1: gates(t) complete

        // ===== fused phase: LSTM+phi+attn (redundant per b) + ctx GEMV =====
        {
            const float* cin  = g_cbuf[t & 1]       + b2 * DD;
            float*       cout = g_cbuf[(t & 1) ^ 1] + b2 * DD;

            {
                const int e = tid;   // pair index, 0..511
                const float2* gb = reinterpret_cast<const float2*>(g_bias);
                float2 gi = gb[e],        gf = gb[512 + e];
                float2 gg = gb[1024 + e], go = gb[1536 + e];
                #pragma unroll
                for (int q = 0; q < KSPLIT; ++q) {
                    const float2* gp = reinterpret_cast<const float2*>(g_gpart[q][b2]);
                    float2 v;
                    v = gp[e];        gi.x += v.x; gi.y += v.y;
                    v = gp[512 + e];  gf.x += v.x; gf.y += v.y;
                    v = gp[1024 + e]; gg.x += v.x; gg.y += v.y;
                    v = gp[1536 + e]; go.x += v.x; go.y += v.y;
                }
                const float2 cold = reinterpret_cast<const float2*>(cin)[e];
                float2 cn, hn;
                cn.x = sigf(gf.x) * cold.x + sigf(gi.x) * tanhfast(gg.x);
                cn.y = sigf(gf.y) * cold.y + sigf(gi.y) * tanhfast(gg.y);
                hn.x = sigf(go.x) * tanhfast(cn.x);
                hn.y = sigf(go.y) * tanhfast(cn.y);
                reinterpret_cast<float2*>(sh_h)[e] = hn;
                // distributed state write: slice sl8 owns pair range
                if ((e >> 6) == sl8) {
                    reinterpret_cast<float2*>(cout)[e] = cn;
                    reinterpret_cast<float2*>(g_h + b2 * DD)[e] = hn;
                }
            }
            __syncthreads();

            // phi = h @ Wg_w^T + Wg_b  (16 warps x 3 rows)
            {
                const int w = tid >> 5, lane = tid & 31;
                float hreg[32];
                #pragma unroll
                for (int i = 0; i < 32; ++i) hreg[i] = sh_h[i * 32 + lane];
                #pragma unroll
                for (int mi = 0; mi < 3; ++mi) {
                    const int mm = w * 3 + mi;
                    const float* wr = Wg_w + (size_t)mm * DD;
                    float acc = 0.0f;
                    #pragma unroll
                    for (int i = 0; i < 32; ++i) acc += wr[i * 32 + lane] * hreg[i];
                    #pragma unroll
                    for (int off = 16; off; off >>= 1)
                        acc += __shfl_xor_sync(0xFFFFFFFFu, acc, off);
                    if (lane == 0) sh_phi[mm] = acc + Wg_b[mm];
                }
            }
            __syncthreads();

            if (tid < 32) {
                const int m = tid & 15;
                const float pk = sh_phi[m];
                const float pb = sh_phi[MM + m];
                const float pa = sh_phi[2 * MM + m];
                float mx = pa;
                #pragma unroll
                for (int off = 1; off < 16; off <<= 1)
                    mx = fmaxf(mx, __shfl_xor_sync(0xFFFFFFFFu, mx, off, 16));
                const float e = __expf(pa - mx);
                float sum = e;
                #pragma unroll
                for (int off = 1; off < 16; off <<= 1)
                    sum += __shfl_xor_sync(0xFFFFFFFFu, sum, off, 16);
                if (tid < 16) {
                    sh_alpha[m] = e / sum;
                    sh_ksi[m]   = __expf(pk);
                    sh_binv[m]  = __expf(-pb);
                }
            }
            __syncthreads();

            // attention weights (one s per thread) + active-span detection
            {
                const int s = tid;            // NT == SS
                const int w = tid >> 5, lane = tid & 31;
                const float fs = (float)s;
                float aw = 0.0f, ar = 0.0f;
                #pragma unroll
                for (int m = 0; m < MM; ++m) {
                    const float binv = sh_binv[m];
                    const float z  = (fs - sh_ksi[m]) * binv;
                    const float hb = 0.5f * binv;
                    const float fr = sigf(z + hb);
                    const float fl = sigf(z - hb);
                    const float al = sh_alpha[m];
                    aw += al * (fr - fl);
                    ar += al * fr;
                }
                sh_watt[s] = aw;
                const bool act = (aw > 1e-8f);
                int slo = act ? s : SS;
                int shi = act ? s : -1;
                #pragma unroll
                for (int off = 16; off; off >>= 1) {
                    slo = min(slo, __shfl_xor_sync(0xFFFFFFFFu, slo, off));
                    shi = max(shi, __shfl_xor_sync(0xFFFFFFFFu, shi, off));
                }
                if (lane == 0) { sh_lo[w] = slo; sh_hi[w] = shi; }
                // distributed align writes: slice sl8 owns s range [sl8*64, +64)
                if ((s >> 6) == sl8)
                    out_align[((size_t)b2 * TT + t) * SS + s] = aw;
                if (sl8 == 0 && t == TT - 1 && s == lens[b2] - 1)
                    out_term[b2] = 1.0f - ar;
            }
            __syncthreads();

            // ctx GEMV over the active span, split evenly over 16 warps
            {
                const int w = tid >> 5, lane = tid & 31;
                int slo = sh_lo[0], shi = sh_hi[0];
                #pragma unroll
                for (int i = 1; i < 16; ++i) {
                    slo = min(slo, sh_lo[i]);
                    shi = max(shi, sh_hi[i]);
                }
                float4 acc = make_float4(0.f, 0.f, 0.f, 0.f);
                if (shi >= slo) {
                    const int R   = shi - slo + 1;
                    const int cnt = (R + 15) >> 4;           // per warp
                    const int s0  = slo + w * cnt;
                    const int s1  = min(s0 + cnt, shi + 1);
                    const float* mb = memv + (size_t)b2 * SS * DD + d0 + lane * 4;
                    for (int s = s0; s < s1; ++s) {
                        const float wv = sh_watt[s];
                        const float4 mv = *reinterpret_cast<const float4*>(mb + (size_t)s * DD);
                        acc.x += wv * mv.x; acc.y += wv * mv.y;
                        acc.z += wv * mv.z; acc.w += wv * mv.w;
                    }
                }
                red[w * 32 + lane] = acc;
                __syncthreads();
                if (tid < 32) {
                    float4 r = red[tid];
                    #pragma unroll
                    for (int q = 1; q < 16; ++q) {
                        const float4 v = red[q * 32 + tid];
                        r.x += v.x; r.y += v.y; r.z += v.z; r.w += v.w;
                    }
                    const int di = d0 + tid * 4;
                    *reinterpret_cast<float4*>(&g_ctx[b2 * DD + di]) = r;
                    if (t == TT - 1)
                        *reinterpret_cast<float4*>(&out_ctx[b2 * DD + di]) = r;
                }
            }
        }
        grid_barrier(++bgen);  // B3: h, c, ctx ready for next step
    }
}

extern "C" void kernel_launch(void* const* d_in, const int* in_sizes, int n_in,
                              void* d_out, int out_size) {
    (void)in_sizes; (void)n_in; (void)out_size;
    const float* x_in  = (const float*)d_in[0];
    const float* memv  = (const float*)d_in[1];
    const int*   lens  = (const int*)  d_in[2];
    const float* W_ih  = (const float*)d_in[3];
    const float* W_hh  = (const float*)d_in[4];
    const float* b_ih  = (const float*)d_in[5];
    const float* b_hh  = (const float*)d_in[6];
    const float* Wg_w  = (const float*)d_in[7];
    const float* Wg_b  = (const float*)d_in[8];
    tts_kernel<<<NB, NT, 40960>>>(x_in, memv, lens, W_ih, W_hh,
                                  b_ih, b_hh, Wg_w, Wg_b, (float*)d_out);
}